// round 5
// baseline (speedup 1.0000x reference)
#include <cuda_runtime.h>
#include <cuda_fp16.h>
#include <math.h>
#include <stdint.h>

// Problem dims
#define T_DIM 512
#define B_DIM 32
#define E_DIM 512
#define H_DIM 2048

// Tiling
#define HC  32          // h channels per CTA
#define NT  96          // GEMM N = 3*HC (z|f|o)
#define MT  128         // t-chunk (GEMM M)
#define KC  64          // K elems per smem chunk (fp16 -> 128B rows)
#define NKC 8           // K chunks per t-chunk (512/64)
#define NTC 4           // t-chunks (512/128)
#define NCH (NTC * NKC) // 32 chunks total
#define NSTG 3          // pipeline stages

#define ACT_STRIDE 104  // act row stride in halves (208B = 52 words)

// ---- smem layout (bytes) ----
#define SM_A    0                    // 3 x 16384  (A stages, fp16 SW128)
#define SM_B    49152                // 3 x 12288  (W stages, fp16 SW128)
#define SM_ACT  86016                // 128 x 104 x 2 = 26624 (fp16)
#define SM_BIAS 112640               // 96 floats
#define SMEM_BYTES 113024

#define SWZ128(x) ((x) ^ (((x) >> 3) & 0x70))

// fp16 scratch (static device allocations — allowed)
__device__ __half g_sentH[B_DIM * T_DIM * E_DIM];   // (B,T,E) fp16
__device__ __half g_wH[3 * H_DIM * E_DIM];          // (3H,E)  fp16

// ---------------- helpers ----------------
__device__ __forceinline__ uint32_t smem_u32(const void* p) {
    uint32_t a;
    asm("{ .reg .u64 t; cvta.to.shared.u64 t, %1; cvt.u32.u64 %0, t; }" : "=r"(a) : "l"(p));
    return a;
}
__device__ __forceinline__ float tanh_hw(float x) {
    float y; asm("tanh.approx.f32 %0, %1;" : "=f"(y) : "f"(x)); return y;
}
__device__ __forceinline__ float sigmoid_hw(float x) {
    return fmaf(0.5f, tanh_hw(0.5f * x), 0.5f);
}
__device__ __forceinline__ void cp_async16(uint32_t dst, const void* src) {
    uint64_t g; asm("cvta.to.global.u64 %0, %1;" : "=l"(g) : "l"(src));
    asm volatile("cp.async.cg.shared.global [%0], [%1], 16;" :: "r"(dst), "l"(g) : "memory");
}
__device__ __forceinline__ void ldsm4(uint32_t* r, uint32_t addr) {
    asm volatile("ldmatrix.sync.aligned.m8n8.x4.shared.b16 {%0,%1,%2,%3}, [%4];"
                 : "=r"(r[0]), "=r"(r[1]), "=r"(r[2]), "=r"(r[3]) : "r"(addr));
}
__device__ __forceinline__ void mma_f16(float* c, const uint32_t* a, const uint32_t* b) {
    asm volatile(
        "mma.sync.aligned.m16n8k16.row.col.f32.f16.f16.f32 "
        "{%0,%1,%2,%3}, {%4,%5,%6,%7}, {%8,%9}, {%0,%1,%2,%3};"
        : "+f"(c[0]), "+f"(c[1]), "+f"(c[2]), "+f"(c[3])
        : "r"(a[0]), "r"(a[1]), "r"(a[2]), "r"(a[3]), "r"(b[0]), "r"(b[1]));
}

// ---------- merged prepass: fp32 -> fp16; sent also transposed (T,B,E)->(B,T,E) ----------
#define SENT_F4 (T_DIM * B_DIM * E_DIM / 4)   // 2,097,152
#define W_F4    (3 * H_DIM * E_DIM / 4)       //   786,432
__global__ void __launch_bounds__(256) prep_all(const float* __restrict__ sent,
                                                const float* __restrict__ W) {
    int li = blockIdx.x * 256 + threadIdx.x;
    if (li < SENT_F4) {
        const float4 v = ((const float4*)sent)[li];
        int e4 = li & 127;
        int b  = (li >> 7) & 31;
        int t  = li >> 12;
        __half2* dst = (__half2*)(g_sentH + ((size_t)(b * T_DIM + t) * E_DIM + e4 * 4));
        dst[0] = __floats2half2_rn(v.x, v.y);
        dst[1] = __floats2half2_rn(v.z, v.w);
    } else if (li < SENT_F4 + W_F4) {
        int wi = li - SENT_F4;
        const float4 v = ((const float4*)W)[wi];
        __half2* dst = (__half2*)g_wH + (size_t)wi * 2;
        dst[0] = __floats2half2_rn(v.x, v.y);
        dst[1] = __floats2half2_rn(v.z, v.w);
    }
}

// ---------------- main fused kernel: 128 threads, 4 warps (2M x 2N), warp tile 64x48 ----------------
__global__ void __launch_bounds__(128, 2)
qrnn_f16_kernel(const float* __restrict__ bias, float* __restrict__ out)
{
    extern __shared__ char smem[];
    const uint32_t sb = smem_u32(smem);
    const int tid = threadIdx.x;
    const int bb  = blockIdx.y;
    const int h0  = blockIdx.x * HC;
    const int lane = tid & 31;
    const int wid  = tid >> 5;
    const int g  = lane >> 2;
    const int tg = lane & 3;
    const int wm = wid & 1;          // 2 warps in M
    const int wn = wid >> 1;         // 2 warps in N
    const int m_base = wm * 64;      // 4 m-frags of 16
    const int n_base = wn * 48;      // 6 n-frags of 8

    float*  sbias = (float*)(smem + SM_BIAS);
    __half* act   = (__half*)(smem + SM_ACT);
    if (tid < 96) sbias[tid] = bias[(tid >> 5) * H_DIM + h0 + (tid & 31)];

    const __half* Asrc = g_sentH + (size_t)bb * (T_DIM * E_DIM);

    // per-lane ldmatrix address components
    const int am = lane >> 3;
    const int a_row_in = (am & 1) * 8 + (lane & 7);   // row within m16 frag
    const int a_colb16 = (am >> 1) * 16;              // k-half byte offset
    const int b_row_in = (am >> 1) * 8 + (lane & 7);  // n within n16 pair
    const int b_colb16 = (am & 1) * 16;

    // stage chunk ch into ring slot ch%3; per-thread commit_group
    auto stage = [&](int ch) {
        const int tc = ch >> 3, kc = ch & 7, slot = ch % NSTG;
        const __half* ab = Asrc + (size_t)(tc * MT) * E_DIM + kc * KC;
        const uint32_t aB = sb + SM_A + slot * 16384;
#pragma unroll
        for (int i = 0; i < 8; i++) {
            int l = i * 128 + tid;
            int row = l >> 3, c = l & 7;
            cp_async16(aB + (uint32_t)SWZ128(row * 128 + c * 16), ab + (size_t)row * E_DIM + c * 8);
        }
        const uint32_t bB = sb + SM_B + slot * 12288;
#pragma unroll
        for (int i = 0; i < 6; i++) {
            int l = i * 128 + tid;
            int n = l >> 3, c = l & 7;
            int wrow = (n >> 5) * H_DIM + h0 + (n & 31);
            cp_async16(bB + (uint32_t)SWZ128(n * 128 + c * 16),
                       g_wH + (size_t)wrow * E_DIM + kc * KC + c * 8);
        }
        asm volatile("cp.async.commit_group;" ::: "memory");
    };

    float c_state = 0.0f;
    float m_state = -INFINITY;

    stage(0);
    stage(1);

    for (int tc = 0; tc < NTC; tc++) {
        float acc[4][6][4];
#pragma unroll
        for (int mf = 0; mf < 4; mf++)
#pragma unroll
            for (int nf = 0; nf < 6; nf++)
#pragma unroll
                for (int q = 0; q < 4; q++) acc[mf][nf][q] = 0.0f;

        for (int kc = 0; kc < NKC; kc++) {
            const int ch   = tc * NKC + kc;
            const int slot = ch % NSTG;

            if (ch < NCH - 1) { asm volatile("cp.async.wait_group 1;" ::: "memory"); }
            else              { asm volatile("cp.async.wait_group 0;" ::: "memory"); }
            __syncthreads();   // chunk ch staged by all threads; slot (ch+2)%3 readers done
            if (ch + 2 < NCH) stage(ch + 2);   // async; overlaps MMAs below

            const uint32_t aB = sb + SM_A + slot * 16384;
            const uint32_t bB = sb + SM_B + slot * 12288;
#pragma unroll
            for (int ks = 0; ks < 4; ks++) {     // 4 k16-steps over KC=64
                uint32_t a[4][4];
#pragma unroll
                for (int mf = 0; mf < 4; mf++) {
                    int row  = m_base + mf * 16 + a_row_in;
                    int colb = ks * 32 + a_colb16;
                    ldsm4(a[mf], aB + (uint32_t)SWZ128(row * 128 + colb));
                }
                uint32_t b[6][2];
#pragma unroll
                for (int p = 0; p < 3; p++) {
                    int nrow = n_base + p * 16 + b_row_in;
                    int colb = ks * 32 + b_colb16;
                    uint32_t r[4];
                    ldsm4(r, bB + (uint32_t)SWZ128(nrow * 128 + colb));
                    b[2 * p][0] = r[0];     b[2 * p][1] = r[1];
                    b[2 * p + 1][0] = r[2]; b[2 * p + 1][1] = r[3];
                }
#pragma unroll
                for (int mf = 0; mf < 4; mf++)
#pragma unroll
                    for (int nf = 0; nf < 6; nf++)
                        mma_f16(acc[mf][nf], a[mf], b[nf]);
            }
        }

        // ---- epilogue: bias + activation -> act (fp16, half2 stores) ----
        // ACT was last read by scan of tc-1, separated by the 8 chunk barriers above.
#pragma unroll
        for (int mf = 0; mf < 4; mf++) {
            int r0 = m_base + mf * 16 + g;
#pragma unroll
            for (int nf = 0; nf < 6; nf++) {
                int j   = n_base + nf * 8 + tg * 2;
                int grp = j >> 5;
#pragma unroll
                for (int rr = 0; rr < 2; rr++) {
                    int row  = r0 + rr * 8;
                    float v0 = acc[mf][nf][rr * 2 + 0] + sbias[j];
                    float v1 = acc[mf][nf][rr * 2 + 1] + sbias[j + 1];
                    if (grp == 0) { v0 = tanh_hw(v0);    v1 = tanh_hw(v1); }
                    else          { v0 = sigmoid_hw(v0); v1 = sigmoid_hw(v1); }
                    *(__half2*)(act + row * ACT_STRIDE + j) = __floats2half2_rn(v0, v1);
                }
            }
        }
        __syncthreads();

        // ---- scan: threads 0..31, one h each, sequential over the chunk ----
        if (tid < HC) {
#pragma unroll 8
            for (int t = 0; t < MT; t++) {
                float z = __half2float(act[t * ACT_STRIDE + tid]);
                float f = __half2float(act[t * ACT_STRIDE + 32 + tid]);
                float o = __half2float(act[t * ACT_STRIDE + 64 + tid]);
                c_state = fmaf(f, z - c_state, c_state);   // c = f*z + (1-f)*c
                m_state = fmaxf(m_state, o * c_state);
            }
        }
        // next chunk's barrier orders scan before the following epilogue's writes
    }

    if (tid < HC) out[bb * H_DIM + h0 + tid] = m_state;
}

extern "C" void kernel_launch(void* const* d_in, const int* in_sizes, int n_in,
                              void* d_out, int out_size)
{
    (void)in_sizes; (void)n_in; (void)out_size;
    const float* sent = (const float*)d_in[0];   // (T,B,E) fp32
    const float* W    = (const float*)d_in[2];   // (3H,E)  fp32
    const float* bias = (const float*)d_in[3];   // (3H)    fp32
    float* out = (float*)d_out;                  // (B,H)   fp32

    cudaFuncSetAttribute(qrnn_f16_kernel, cudaFuncAttributeMaxDynamicSharedMemorySize, SMEM_BYTES);

    prep_all<<<(SENT_F4 + W_F4 + 255) / 256, 256>>>(sent, W);
    qrnn_f16_kernel<<<dim3(H_DIM / HC, B_DIM), 128, SMEM_BYTES>>>(bias, out);
}

// round 6
// speedup vs baseline: 1.1048x; 1.1048x over previous
#include <cuda_runtime.h>
#include <cuda_fp16.h>
#include <math.h>
#include <stdint.h>

// Problem dims
#define T_DIM 512
#define B_DIM 32
#define E_DIM 512
#define H_DIM 2048

// Tiling
#define HC  32          // h channels per CTA
#define NT  96          // GEMM N = 3*HC (z|f|o)
#define MT  128         // t-chunk (GEMM M)
#define KC  64          // K elems per smem chunk (fp16 -> 128B rows)
#define NKC 8           // K chunks per t-chunk (512/64)
#define NTC 4           // t-chunks (512/128)
#define NCH (NTC * NKC) // 32 chunks total

#define ACT_STRIDE 104  // act row stride in halves (208B)

// ---- smem layout (bytes) ----
#define SM_A    0                    // 2 x 16384  (A stages, fp16 SW128)
#define SM_B    32768                // 2 x 12288  (W stages, fp16 SW128)
#define SM_ACT  57344                // 128 x 104 x 2 = 26624 (fp16)
#define SM_BIAS 83968                // 96 floats = 384
#define SM_SEGA 84352                // 4 x 32 floats = 512
#define SM_SEGB 84864                // 4 x 32 floats = 512
#define SMEM_BYTES 85504

#define SWZ128(x) ((x) ^ (((x) >> 3) & 0x70))

// fp16 scratch (static device allocations — allowed)
__device__ __half g_sentH[B_DIM * T_DIM * E_DIM];   // (B,T,E) fp16
__device__ __half g_wH[3 * H_DIM * E_DIM];          // (3H,E)  fp16

// ---------------- helpers ----------------
__device__ __forceinline__ uint32_t smem_u32(const void* p) {
    uint32_t a;
    asm("{ .reg .u64 t; cvta.to.shared.u64 t, %1; cvt.u32.u64 %0, t; }" : "=r"(a) : "l"(p));
    return a;
}
__device__ __forceinline__ float tanh_hw(float x) {
    float y; asm("tanh.approx.f32 %0, %1;" : "=f"(y) : "f"(x)); return y;
}
__device__ __forceinline__ float sigmoid_hw(float x) {
    return fmaf(0.5f, tanh_hw(0.5f * x), 0.5f);
}
__device__ __forceinline__ void cp_async16(uint32_t dst, const void* src) {
    uint64_t g; asm("cvta.to.global.u64 %0, %1;" : "=l"(g) : "l"(src));
    asm volatile("cp.async.cg.shared.global [%0], [%1], 16;" :: "r"(dst), "l"(g) : "memory");
}
__device__ __forceinline__ void ldsm4(uint32_t* r, uint32_t addr) {
    asm volatile("ldmatrix.sync.aligned.m8n8.x4.shared.b16 {%0,%1,%2,%3}, [%4];"
                 : "=r"(r[0]), "=r"(r[1]), "=r"(r[2]), "=r"(r[3]) : "r"(addr));
}
__device__ __forceinline__ void mma_f16(float* c, const uint32_t* a, const uint32_t* b) {
    asm volatile(
        "mma.sync.aligned.m16n8k16.row.col.f32.f16.f16.f32 "
        "{%0,%1,%2,%3}, {%4,%5,%6,%7}, {%8,%9}, {%0,%1,%2,%3};"
        : "+f"(c[0]), "+f"(c[1]), "+f"(c[2]), "+f"(c[3])
        : "r"(a[0]), "r"(a[1]), "r"(a[2]), "r"(a[3]), "r"(b[0]), "r"(b[1]));
}

// ---------- merged prepass: fp32 -> fp16; sent also transposed (T,B,E)->(B,T,E) ----------
#define SENT_F4 (T_DIM * B_DIM * E_DIM / 4)   // 2,097,152
#define W_F4    (3 * H_DIM * E_DIM / 4)       //   786,432
__global__ void __launch_bounds__(256) prep_all(const float* __restrict__ sent,
                                                const float* __restrict__ W) {
    int li = blockIdx.x * 256 + threadIdx.x;
    if (li < SENT_F4) {
        const float4 v = ((const float4*)sent)[li];
        int e4 = li & 127;
        int b  = (li >> 7) & 31;
        int t  = li >> 12;
        __half2* dst = (__half2*)(g_sentH + ((size_t)(b * T_DIM + t) * E_DIM + e4 * 4));
        dst[0] = __floats2half2_rn(v.x, v.y);
        dst[1] = __floats2half2_rn(v.z, v.w);
    } else if (li < SENT_F4 + W_F4) {
        int wi = li - SENT_F4;
        const float4 v = ((const float4*)W)[wi];
        __half2* dst = (__half2*)g_wH + (size_t)wi * 2;
        dst[0] = __floats2half2_rn(v.x, v.y);
        dst[1] = __floats2half2_rn(v.z, v.w);
    }
}

// ---------------- main fused kernel: 128 threads, 4 warps (2M x 2N), warp tile 64x48 ----------------
__global__ void __launch_bounds__(128, 2)
qrnn_f16_kernel(const float* __restrict__ bias, float* __restrict__ out)
{
    extern __shared__ char smem[];
    const uint32_t sb = smem_u32(smem);
    const int tid = threadIdx.x;
    const int bb  = blockIdx.y;
    const int h0  = blockIdx.x * HC;
    const int lane = tid & 31;
    const int wid  = tid >> 5;
    const int g  = lane >> 2;
    const int tg = lane & 3;
    const int wm = wid & 1;          // 2 warps in M
    const int wn = wid >> 1;         // 2 warps in N
    const int m_base = wm * 64;      // 4 m-frags of 16
    const int n_base = wn * 48;      // 6 n-frags of 8

    float*  sbias = (float*)(smem + SM_BIAS);
    __half* act   = (__half*)(smem + SM_ACT);
    float*  segA  = (float*)(smem + SM_SEGA);   // [4][32]
    float*  segB  = (float*)(smem + SM_SEGB);   // [4][32]
    if (tid < 96) sbias[tid] = bias[(tid >> 5) * H_DIM + h0 + (tid & 31)];

    const __half* Asrc = g_sentH + (size_t)bb * (T_DIM * E_DIM);

    // per-lane ldmatrix address components
    const int am = lane >> 3;
    const int a_row_in = (am & 1) * 8 + (lane & 7);
    const int a_colb16 = (am >> 1) * 16;
    const int b_row_in = (am >> 1) * 8 + (lane & 7);
    const int b_colb16 = (am & 1) * 16;

    // stage chunk (tc, kc) into buffer buf
    auto stage = [&](int tc, int kc, int buf) {
        const __half* ab = Asrc + (size_t)(tc * MT) * E_DIM + kc * KC;
        const uint32_t aB = sb + SM_A + buf * 16384;
#pragma unroll
        for (int i = 0; i < 8; i++) {
            int l = i * 128 + tid;
            int row = l >> 3, c = l & 7;
            cp_async16(aB + (uint32_t)SWZ128(row * 128 + c * 16), ab + (size_t)row * E_DIM + c * 8);
        }
        const uint32_t bB = sb + SM_B + buf * 12288;
#pragma unroll
        for (int i = 0; i < 6; i++) {
            int l = i * 128 + tid;
            int n = l >> 3, c = l & 7;
            int wrow = (n >> 5) * H_DIM + h0 + (n & 31);
            cp_async16(bB + (uint32_t)SWZ128(n * 128 + c * 16),
                       g_wH + (size_t)wrow * E_DIM + kc * KC + c * 8);
        }
        asm volatile("cp.async.commit_group;" ::: "memory");
    };

    // scan state: warp wid owns t-segment [32*wid, 32*wid+32) of each chunk; lane owns channel h=lane
    float c_carry = 0.0f;        // replicated across the 4 warps (identical computation)
    float m_state = -INFINITY;

    stage(0, 0, 0);

    for (int tc = 0; tc < NTC; tc++) {
        float acc[4][6][4];
#pragma unroll
        for (int mf = 0; mf < 4; mf++)
#pragma unroll
            for (int nf = 0; nf < 6; nf++)
#pragma unroll
                for (int q = 0; q < 4; q++) acc[mf][nf][q] = 0.0f;

        for (int kc = 0; kc < NKC; kc++) {
            const int ch  = tc * NKC + kc;
            const int buf = ch & 1;

            __syncthreads();   // alt buffer's MMA readers (chunk ch-1) done
            if (ch + 1 < NCH) {
                stage((ch + 1) >> 3, (ch + 1) & 7, (ch + 1) & 1);
                asm volatile("cp.async.wait_group 1;" ::: "memory");
            } else {
                asm volatile("cp.async.wait_group 0;" ::: "memory");
            }
            __syncthreads();   // chunk ch fully staged

            const uint32_t aB = sb + SM_A + buf * 16384;
            const uint32_t bB = sb + SM_B + buf * 12288;
#pragma unroll
            for (int ks = 0; ks < 4; ks++) {     // 4 k16-steps over KC=64
                uint32_t a[4][4];
#pragma unroll
                for (int mf = 0; mf < 4; mf++) {
                    int row  = m_base + mf * 16 + a_row_in;
                    int colb = ks * 32 + a_colb16;
                    ldsm4(a[mf], aB + (uint32_t)SWZ128(row * 128 + colb));
                }
                uint32_t b[6][2];
#pragma unroll
                for (int p = 0; p < 3; p++) {
                    int nrow = n_base + p * 16 + b_row_in;
                    int colb = ks * 32 + b_colb16;
                    uint32_t r[4];
                    ldsm4(r, bB + (uint32_t)SWZ128(nrow * 128 + colb));
                    b[2 * p][0] = r[0];     b[2 * p][1] = r[1];
                    b[2 * p + 1][0] = r[2]; b[2 * p + 1][1] = r[3];
                }
#pragma unroll
                for (int mf = 0; mf < 4; mf++)
#pragma unroll
                    for (int nf = 0; nf < 6; nf++)
                        mma_f16(acc[mf][nf], a[mf], b[nf]);
            }
        }

        // ---- epilogue: bias + activation -> act (fp16 half2) ----
        // prior t-chunk's scan reads of act/seg are >=16 barriers back — safe to overwrite
#pragma unroll
        for (int mf = 0; mf < 4; mf++) {
            int r0 = m_base + mf * 16 + g;
#pragma unroll
            for (int nf = 0; nf < 6; nf++) {
                int j   = n_base + nf * 8 + tg * 2;
                int grp = j >> 5;
#pragma unroll
                for (int rr = 0; rr < 2; rr++) {
                    int row  = r0 + rr * 8;
                    float v0 = acc[mf][nf][rr * 2 + 0] + sbias[j];
                    float v1 = acc[mf][nf][rr * 2 + 1] + sbias[j + 1];
                    if (grp == 0) { v0 = tanh_hw(v0);    v1 = tanh_hw(v1); }
                    else          { v0 = sigmoid_hw(v0); v1 = sigmoid_hw(v1); }
                    *(__half2*)(act + row * ACT_STRIDE + j) = __floats2half2_rn(v0, v1);
                }
            }
        }
        __syncthreads();

        // ---- parallel segmented scan: warp = t-segment, lane = channel ----
        const int t0s = wid * 32;
        // pass 1: compose segment affine (A, B):  c_out = A*c_in + B
        float Aseg = 1.0f, Bseg = 0.0f;
#pragma unroll 8
        for (int i = 0; i < 32; i++) {
            const __half* rowp = act + (t0s + i) * ACT_STRIDE;
            float z = __half2float(rowp[lane]);
            float f = __half2float(rowp[32 + lane]);
            float a = 1.0f - f;
            Aseg *= a;
            Bseg = fmaf(a, Bseg, f * z);
        }
        segA[wid * 32 + lane] = Aseg;
        segB[wid * 32 + lane] = Bseg;
        __syncthreads();

        // c at entry of my segment: apply preceding segments to the carry
        float c = c_carry;
        for (int s = 0; s < wid; s++)
            c = fmaf(segA[s * 32 + lane], c, segB[s * 32 + lane]);
        // pass 2: walk my 32 t's, compute c_t and running max of o*c
#pragma unroll 8
        for (int i = 0; i < 32; i++) {
            const __half* rowp = act + (t0s + i) * ACT_STRIDE;
            float z = __half2float(rowp[lane]);
            float f = __half2float(rowp[32 + lane]);
            float o = __half2float(rowp[64 + lane]);
            c = fmaf(f, z - c, c);                 // c = f*z + (1-f)*c
            m_state = fmaxf(m_state, o * c);
        }
        // advance carry over the whole chunk (replicated, identical in all warps)
#pragma unroll
        for (int s = 0; s < 4; s++)
            c_carry = fmaf(segA[s * 32 + lane], c_carry, segB[s * 32 + lane]);
        // next t-chunk's k-loop barriers order these reads before seg overwrite
    }

    // final: max across the 4 segment-threads of each channel
    __syncthreads();                    // seg reads done; reuse segA as staging
    segA[wid * 32 + lane] = m_state;
    __syncthreads();
    if (wid == 0) {
        float r = fmaxf(fmaxf(segA[lane], segA[32 + lane]),
                        fmaxf(segA[64 + lane], segA[96 + lane]));
        out[bb * H_DIM + h0 + lane] = r;
    }
}

extern "C" void kernel_launch(void* const* d_in, const int* in_sizes, int n_in,
                              void* d_out, int out_size)
{
    (void)in_sizes; (void)n_in; (void)out_size;
    const float* sent = (const float*)d_in[0];   // (T,B,E) fp32
    const float* W    = (const float*)d_in[2];   // (3H,E)  fp32
    const float* bias = (const float*)d_in[3];   // (3H)    fp32
    float* out = (float*)d_out;                  // (B,H)   fp32

    cudaFuncSetAttribute(qrnn_f16_kernel, cudaFuncAttributeMaxDynamicSharedMemorySize, SMEM_BYTES);

    prep_all<<<(SENT_F4 + W_F4 + 255) / 256, 256>>>(sent, W);
    qrnn_f16_kernel<<<dim3(H_DIM / HC, B_DIM), 128, SMEM_BYTES>>>(bias, out);
}

// round 7
// speedup vs baseline: 1.1276x; 1.0206x over previous
#include <cuda_runtime.h>
#include <cuda_fp16.h>
#include <math.h>
#include <stdint.h>

// Problem dims
#define T_DIM 512
#define B_DIM 32
#define E_DIM 512
#define H_DIM 2048

// Tiling
#define HC  32          // h channels per CTA
#define NT  96          // GEMM N = 3*HC (z|f|o)
#define MT  128         // t-chunk (GEMM M)
#define KC  64          // K elems per smem chunk (fp16 -> 128B rows)
#define NKC 8           // K chunks per t-chunk (512/64)
#define NTC 4           // t-chunks (512/128)
#define NCH (NTC * NKC) // 32 chunks total

#define ACT_STRIDE 104  // act row stride in halves (208B)

// ---- smem layout (bytes) ----
#define SM_A    0                    // 2 x 16384  (A stages, fp16 SW128)
#define SM_B    32768                // 2 x 12288  (W stages, fp16 SW128)
#define SM_ACT  57344                // 128 x 104 x 2 = 26624 (fp16)
#define SM_BIAS 83968                // 96 floats = 384
#define SM_SEGA 84352                // 8 x 32 floats = 1024
#define SM_SEGB 85376                // 8 x 32 floats = 1024
#define SMEM_BYTES 86400

#define SWZ128(x) ((x) ^ (((x) >> 3) & 0x70))

// fp16 scratch (static device allocations — allowed)
__device__ __half g_sentH[B_DIM * T_DIM * E_DIM];   // (B,T,E) fp16
__device__ __half g_wH[3 * H_DIM * E_DIM];          // (3H,E)  fp16

// ---------------- helpers ----------------
__device__ __forceinline__ uint32_t smem_u32(const void* p) {
    uint32_t a;
    asm("{ .reg .u64 t; cvta.to.shared.u64 t, %1; cvt.u32.u64 %0, t; }" : "=r"(a) : "l"(p));
    return a;
}
__device__ __forceinline__ float tanh_hw(float x) {
    float y; asm("tanh.approx.f32 %0, %1;" : "=f"(y) : "f"(x)); return y;
}
__device__ __forceinline__ float sigmoid_hw(float x) {
    return fmaf(0.5f, tanh_hw(0.5f * x), 0.5f);
}
__device__ __forceinline__ void cp_async16(uint32_t dst, const void* src) {
    uint64_t g; asm("cvta.to.global.u64 %0, %1;" : "=l"(g) : "l"(src));
    asm volatile("cp.async.cg.shared.global [%0], [%1], 16;" :: "r"(dst), "l"(g) : "memory");
}
__device__ __forceinline__ void ldsm4(uint32_t* r, uint32_t addr) {
    asm volatile("ldmatrix.sync.aligned.m8n8.x4.shared.b16 {%0,%1,%2,%3}, [%4];"
                 : "=r"(r[0]), "=r"(r[1]), "=r"(r[2]), "=r"(r[3]) : "r"(addr));
}
__device__ __forceinline__ void mma_f16(float* c, const uint32_t* a, const uint32_t* b) {
    asm volatile(
        "mma.sync.aligned.m16n8k16.row.col.f32.f16.f16.f32 "
        "{%0,%1,%2,%3}, {%4,%5,%6,%7}, {%8,%9}, {%0,%1,%2,%3};"
        : "+f"(c[0]), "+f"(c[1]), "+f"(c[2]), "+f"(c[3])
        : "r"(a[0]), "r"(a[1]), "r"(a[2]), "r"(a[3]), "r"(b[0]), "r"(b[1]));
}

// ---------- merged prepass: fp32 -> fp16; sent also transposed (T,B,E)->(B,T,E) ----------
#define SENT_F4 (T_DIM * B_DIM * E_DIM / 4)   // 2,097,152
#define W_F4    (3 * H_DIM * E_DIM / 4)       //   786,432
__global__ void __launch_bounds__(256) prep_all(const float* __restrict__ sent,
                                                const float* __restrict__ W) {
    int li = blockIdx.x * 256 + threadIdx.x;
    if (li < SENT_F4) {
        const float4 v = ((const float4*)sent)[li];
        int e4 = li & 127;
        int b  = (li >> 7) & 31;
        int t  = li >> 12;
        __half2* dst = (__half2*)(g_sentH + ((size_t)(b * T_DIM + t) * E_DIM + e4 * 4));
        dst[0] = __floats2half2_rn(v.x, v.y);
        dst[1] = __floats2half2_rn(v.z, v.w);
    } else if (li < SENT_F4 + W_F4) {
        int wi = li - SENT_F4;
        const float4 v = ((const float4*)W)[wi];
        __half2* dst = (__half2*)g_wH + (size_t)wi * 2;
        dst[0] = __floats2half2_rn(v.x, v.y);
        dst[1] = __floats2half2_rn(v.z, v.w);
    }
}

// -------- main fused kernel: 256 threads, 8 warps (4M x 2N), warp tile 32x48 --------
__global__ void __launch_bounds__(256, 2)
qrnn_f16_kernel(const float* __restrict__ bias, float* __restrict__ out)
{
    extern __shared__ char smem[];
    const uint32_t sb = smem_u32(smem);
    const int tid = threadIdx.x;
    const int bb  = blockIdx.y;
    const int h0  = blockIdx.x * HC;
    const int lane = tid & 31;
    const int wid  = tid >> 5;
    const int g  = lane >> 2;
    const int tg = lane & 3;
    const int wm = wid & 3;          // 4 warps in M
    const int wn = wid >> 2;         // 2 warps in N
    const int m_base = wm * 32;      // 2 m-frags of 16
    const int n_base = wn * 48;      // 6 n-frags of 8

    float*  sbias = (float*)(smem + SM_BIAS);
    __half* act   = (__half*)(smem + SM_ACT);
    float*  segA  = (float*)(smem + SM_SEGA);   // [8][32]
    float*  segB  = (float*)(smem + SM_SEGB);   // [8][32]
    if (tid < 96) sbias[tid] = bias[(tid >> 5) * H_DIM + h0 + (tid & 31)];

    const __half* Asrc = g_sentH + (size_t)bb * (T_DIM * E_DIM);

    // per-lane ldmatrix address components
    const int am = lane >> 3;
    const int a_row_in = (am & 1) * 8 + (lane & 7);
    const int a_colb16 = (am >> 1) * 16;
    const int b_row_in = (am >> 1) * 8 + (lane & 7);
    const int b_colb16 = (am & 1) * 16;

    // stage chunk (tc, kc) into buffer buf (256 threads)
    auto stage = [&](int tc, int kc, int buf) {
        const __half* ab = Asrc + (size_t)(tc * MT) * E_DIM + kc * KC;
        const uint32_t aB = sb + SM_A + buf * 16384;
#pragma unroll
        for (int i = 0; i < 4; i++) {
            int l = i * 256 + tid;
            int row = l >> 3, c = l & 7;
            cp_async16(aB + (uint32_t)SWZ128(row * 128 + c * 16), ab + (size_t)row * E_DIM + c * 8);
        }
        const uint32_t bB = sb + SM_B + buf * 12288;
#pragma unroll
        for (int i = 0; i < 3; i++) {
            int l = i * 256 + tid;
            int n = l >> 3, c = l & 7;
            int wrow = (n >> 5) * H_DIM + h0 + (n & 31);
            cp_async16(bB + (uint32_t)SWZ128(n * 128 + c * 16),
                       g_wH + (size_t)wrow * E_DIM + kc * KC + c * 8);
        }
        asm volatile("cp.async.commit_group;" ::: "memory");
    };

    // scan: warp wid owns t-segment [16*wid, 16*wid+16); lane owns channel h=lane
    float c_carry = 0.0f;        // replicated across warps
    float m_state = -INFINITY;

    stage(0, 0, 0);

    for (int tc = 0; tc < NTC; tc++) {
        float acc[2][6][4];
#pragma unroll
        for (int mf = 0; mf < 2; mf++)
#pragma unroll
            for (int nf = 0; nf < 6; nf++)
#pragma unroll
                for (int q = 0; q < 4; q++) acc[mf][nf][q] = 0.0f;

        for (int kc = 0; kc < NKC; kc++) {
            const int ch  = tc * NKC + kc;
            const int buf = ch & 1;

            __syncthreads();   // alt buffer's MMA readers (chunk ch-1) done
            if (ch + 1 < NCH) {
                stage((ch + 1) >> 3, (ch + 1) & 7, (ch + 1) & 1);
                asm volatile("cp.async.wait_group 1;" ::: "memory");
            } else {
                asm volatile("cp.async.wait_group 0;" ::: "memory");
            }
            __syncthreads();   // chunk ch fully staged

            const uint32_t aB = sb + SM_A + buf * 16384;
            const uint32_t bB = sb + SM_B + buf * 12288;
#pragma unroll
            for (int ks = 0; ks < 4; ks++) {     // 4 k16-steps over KC=64
                uint32_t a[2][4];
#pragma unroll
                for (int mf = 0; mf < 2; mf++) {
                    int row  = m_base + mf * 16 + a_row_in;
                    int colb = ks * 32 + a_colb16;
                    ldsm4(a[mf], aB + (uint32_t)SWZ128(row * 128 + colb));
                }
                uint32_t b[6][2];
#pragma unroll
                for (int p = 0; p < 3; p++) {
                    int nrow = n_base + p * 16 + b_row_in;
                    int colb = ks * 32 + b_colb16;
                    uint32_t r[4];
                    ldsm4(r, bB + (uint32_t)SWZ128(nrow * 128 + colb));
                    b[2 * p][0] = r[0];     b[2 * p][1] = r[1];
                    b[2 * p + 1][0] = r[2]; b[2 * p + 1][1] = r[3];
                }
#pragma unroll
                for (int mf = 0; mf < 2; mf++)
#pragma unroll
                    for (int nf = 0; nf < 6; nf++)
                        mma_f16(acc[mf][nf], a[mf], b[nf]);
            }
        }

        // ---- epilogue: bias + activation -> act (fp16 half2) ----
#pragma unroll
        for (int mf = 0; mf < 2; mf++) {
            int r0 = m_base + mf * 16 + g;
#pragma unroll
            for (int nf = 0; nf < 6; nf++) {
                int j   = n_base + nf * 8 + tg * 2;
                int grp = j >> 5;
#pragma unroll
                for (int rr = 0; rr < 2; rr++) {
                    int row  = r0 + rr * 8;
                    float v0 = acc[mf][nf][rr * 2 + 0] + sbias[j];
                    float v1 = acc[mf][nf][rr * 2 + 1] + sbias[j + 1];
                    if (grp == 0) { v0 = tanh_hw(v0);    v1 = tanh_hw(v1); }
                    else          { v0 = sigmoid_hw(v0); v1 = sigmoid_hw(v1); }
                    *(__half2*)(act + row * ACT_STRIDE + j) = __floats2half2_rn(v0, v1);
                }
            }
        }
        __syncthreads();

        // ---- parallel segmented scan: warp = 16-t segment, lane = channel ----
        const int t0s = wid * 16;
        float Aseg = 1.0f, Bseg = 0.0f;
#pragma unroll
        for (int i = 0; i < 16; i++) {
            const __half* rowp = act + (t0s + i) * ACT_STRIDE;
            float z = __half2float(rowp[lane]);
            float f = __half2float(rowp[32 + lane]);
            float a = 1.0f - f;
            Aseg *= a;
            Bseg = fmaf(a, Bseg, f * z);
        }
        segA[wid * 32 + lane] = Aseg;
        segB[wid * 32 + lane] = Bseg;
        __syncthreads();

        // c at entry of my segment
        float c = c_carry;
        for (int s = 0; s < wid; s++)
            c = fmaf(segA[s * 32 + lane], c, segB[s * 32 + lane]);
        // pass 2: walk my 16 t's
#pragma unroll
        for (int i = 0; i < 16; i++) {
            const __half* rowp = act + (t0s + i) * ACT_STRIDE;
            float z = __half2float(rowp[lane]);
            float f = __half2float(rowp[32 + lane]);
            float o = __half2float(rowp[64 + lane]);
            c = fmaf(f, z - c, c);                 // c = f*z + (1-f)*c
            m_state = fmaxf(m_state, o * c);
        }
        // advance carry over the whole chunk (replicated in all warps)
#pragma unroll
        for (int s = 0; s < 8; s++)
            c_carry = fmaf(segA[s * 32 + lane], c_carry, segB[s * 32 + lane]);
        // next chunk's k-loop barriers order these reads before seg overwrite
    }

    // final: max across the 8 segment-warps of each channel
    __syncthreads();                    // seg reads done; reuse segA as staging
    segA[wid * 32 + lane] = m_state;
    __syncthreads();
    if (wid == 0) {
        float r = m_state;              // wid 0's own
#pragma unroll
        for (int s = 1; s < 8; s++) r = fmaxf(r, segA[s * 32 + lane]);
        out[bb * H_DIM + h0 + lane] = r;
    }
}

extern "C" void kernel_launch(void* const* d_in, const int* in_sizes, int n_in,
                              void* d_out, int out_size)
{
    (void)in_sizes; (void)n_in; (void)out_size;
    const float* sent = (const float*)d_in[0];   // (T,B,E) fp32
    const float* W    = (const float*)d_in[2];   // (3H,E)  fp32
    const float* bias = (const float*)d_in[3];   // (3H)    fp32
    float* out = (float*)d_out;                  // (B,H)   fp32

    cudaFuncSetAttribute(qrnn_f16_kernel, cudaFuncAttributeMaxDynamicSharedMemorySize, SMEM_BYTES);

    prep_all<<<(SENT_F4 + W_F4 + 255) / 256, 256>>>(sent, W);
    qrnn_f16_kernel<<<dim3(H_DIM / HC, B_DIM), 256, SMEM_BYTES>>>(bias, out);
}

// round 8
// speedup vs baseline: 1.1940x; 1.0589x over previous
#include <cuda_runtime.h>
#include <cuda_fp16.h>
#include <math.h>
#include <stdint.h>

// Problem dims
#define T_DIM 512
#define B_DIM 32
#define E_DIM 512
#define H_DIM 2048

// Tiling
#define HC  32          // h channels per CTA
#define NT  96          // GEMM N = 3*HC (z|f|o)
#define MT  64          // t-chunk (GEMM M)
#define KC  64          // K elems per smem chunk (fp16 -> 128B rows)
#define NKC 8           // K chunks per t-chunk (512/64)
#define NTC 8           // t-chunks (512/64)
#define NCH (NTC * NKC) // 64 chunks total

#define ACT_STRIDE 104  // act row stride in halves (208B)

// ---- smem layout (bytes) ----
#define SM_A    0                    // 2 x 8192   (A stages, fp16 SW128)
#define SM_B    16384                // 2 x 12288  (W stages, fp16 SW128)
#define SM_ACT  40960                // 64 x 104 x 2 = 13312 (fp16)
#define SM_BIAS 54272                // 96 floats = 384
#define SM_SEGA 54656                // 4 x 32 floats = 512
#define SM_SEGB 55168                // 4 x 32 floats = 512
#define SMEM_BYTES 55680             // x4 CTAs = 222720 <= 228KB

#define SWZ128(x) ((x) ^ (((x) >> 3) & 0x70))

// fp16 scratch (static device allocations — allowed)
__device__ __half g_sentH[B_DIM * T_DIM * E_DIM];   // (B,T,E) fp16
__device__ __half g_wH[3 * H_DIM * E_DIM];          // (3H,E)  fp16

// ---------------- helpers ----------------
__device__ __forceinline__ uint32_t smem_u32(const void* p) {
    uint32_t a;
    asm("{ .reg .u64 t; cvta.to.shared.u64 t, %1; cvt.u32.u64 %0, t; }" : "=r"(a) : "l"(p));
    return a;
}
__device__ __forceinline__ float tanh_hw(float x) {
    float y; asm("tanh.approx.f32 %0, %1;" : "=f"(y) : "f"(x)); return y;
}
__device__ __forceinline__ float sigmoid_hw(float x) {
    return fmaf(0.5f, tanh_hw(0.5f * x), 0.5f);
}
__device__ __forceinline__ void cp_async16(uint32_t dst, const void* src) {
    uint64_t g; asm("cvta.to.global.u64 %0, %1;" : "=l"(g) : "l"(src));
    asm volatile("cp.async.cg.shared.global [%0], [%1], 16;" :: "r"(dst), "l"(g) : "memory");
}
__device__ __forceinline__ void ldsm4(uint32_t* r, uint32_t addr) {
    asm volatile("ldmatrix.sync.aligned.m8n8.x4.shared.b16 {%0,%1,%2,%3}, [%4];"
                 : "=r"(r[0]), "=r"(r[1]), "=r"(r[2]), "=r"(r[3]) : "r"(addr));
}
__device__ __forceinline__ void mma_f16(float* c, const uint32_t* a, const uint32_t* b) {
    asm volatile(
        "mma.sync.aligned.m16n8k16.row.col.f32.f16.f16.f32 "
        "{%0,%1,%2,%3}, {%4,%5,%6,%7}, {%8,%9}, {%0,%1,%2,%3};"
        : "+f"(c[0]), "+f"(c[1]), "+f"(c[2]), "+f"(c[3])
        : "r"(a[0]), "r"(a[1]), "r"(a[2]), "r"(a[3]), "r"(b[0]), "r"(b[1]));
}

// ---------- merged prepass: fp32 -> fp16; sent also transposed (T,B,E)->(B,T,E) ----------
#define SENT_F4 (T_DIM * B_DIM * E_DIM / 4)   // 2,097,152
#define W_F4    (3 * H_DIM * E_DIM / 4)       //   786,432
__global__ void __launch_bounds__(256) prep_all(const float* __restrict__ sent,
                                                const float* __restrict__ W) {
    int li = blockIdx.x * 256 + threadIdx.x;
    if (li < SENT_F4) {
        const float4 v = ((const float4*)sent)[li];
        int e4 = li & 127;
        int b  = (li >> 7) & 31;
        int t  = li >> 12;
        __half2* dst = (__half2*)(g_sentH + ((size_t)(b * T_DIM + t) * E_DIM + e4 * 4));
        dst[0] = __floats2half2_rn(v.x, v.y);
        dst[1] = __floats2half2_rn(v.z, v.w);
    } else if (li < SENT_F4 + W_F4) {
        int wi = li - SENT_F4;
        const float4 v = ((const float4*)W)[wi];
        __half2* dst = (__half2*)g_wH + (size_t)wi * 2;
        dst[0] = __floats2half2_rn(v.x, v.y);
        dst[1] = __floats2half2_rn(v.z, v.w);
    }
}

// -------- main fused kernel: 128 threads, 4 warps (2M x 2N), warp tile 32x48, occ 4 --------
__global__ void __launch_bounds__(128, 4)
qrnn_f16_kernel(const float* __restrict__ bias, float* __restrict__ out)
{
    extern __shared__ char smem[];
    const uint32_t sb = smem_u32(smem);
    const int tid = threadIdx.x;
    const int bb  = blockIdx.y;
    const int h0  = blockIdx.x * HC;
    const int lane = tid & 31;
    const int wid  = tid >> 5;
    const int g  = lane >> 2;
    const int tg = lane & 3;
    const int wm = wid & 1;          // 2 warps in M
    const int wn = wid >> 1;         // 2 warps in N
    const int m_base = wm * 32;      // 2 m-frags of 16
    const int n_base = wn * 48;      // 6 n-frags of 8

    float*  sbias = (float*)(smem + SM_BIAS);
    __half* act   = (__half*)(smem + SM_ACT);
    float*  segA  = (float*)(smem + SM_SEGA);   // [4][32]
    float*  segB  = (float*)(smem + SM_SEGB);   // [4][32]
    if (tid < 96) sbias[tid] = bias[(tid >> 5) * H_DIM + h0 + (tid & 31)];

    const __half* Asrc = g_sentH + (size_t)bb * (T_DIM * E_DIM);

    // per-lane ldmatrix address components
    const int am = lane >> 3;
    const int a_row_in = (am & 1) * 8 + (lane & 7);
    const int a_colb16 = (am >> 1) * 16;
    const int b_row_in = (am >> 1) * 8 + (lane & 7);
    const int b_colb16 = (am & 1) * 16;

    // stage chunk (tc, kc) into buffer buf (128 threads)
    auto stage = [&](int tc, int kc, int buf) {
        const __half* ab = Asrc + (size_t)(tc * MT) * E_DIM + kc * KC;
        const uint32_t aB = sb + SM_A + buf * 8192;
#pragma unroll
        for (int i = 0; i < 4; i++) {
            int l = i * 128 + tid;
            int row = l >> 3, c = l & 7;
            cp_async16(aB + (uint32_t)SWZ128(row * 128 + c * 16), ab + (size_t)row * E_DIM + c * 8);
        }
        const uint32_t bB = sb + SM_B + buf * 12288;
#pragma unroll
        for (int i = 0; i < 6; i++) {
            int l = i * 128 + tid;
            int n = l >> 3, c = l & 7;
            int wrow = (n >> 5) * H_DIM + h0 + (n & 31);
            cp_async16(bB + (uint32_t)SWZ128(n * 128 + c * 16),
                       g_wH + (size_t)wrow * E_DIM + kc * KC + c * 8);
        }
        asm volatile("cp.async.commit_group;" ::: "memory");
    };

    // scan: warp wid owns t-segment [16*wid, 16*wid+16); lane owns channel h=lane
    float c_carry = 0.0f;        // replicated across warps
    float m_state = -INFINITY;

    stage(0, 0, 0);

    for (int tc = 0; tc < NTC; tc++) {
        float acc[2][6][4];
#pragma unroll
        for (int mf = 0; mf < 2; mf++)
#pragma unroll
            for (int nf = 0; nf < 6; nf++)
#pragma unroll
                for (int q = 0; q < 4; q++) acc[mf][nf][q] = 0.0f;

        for (int kc = 0; kc < NKC; kc++) {
            const int ch  = tc * NKC + kc;
            const int buf = ch & 1;

            __syncthreads();   // alt buffer's MMA readers (chunk ch-1) done
            if (ch + 1 < NCH) {
                stage((ch + 1) >> 3, (ch + 1) & 7, (ch + 1) & 1);
                asm volatile("cp.async.wait_group 1;" ::: "memory");
            } else {
                asm volatile("cp.async.wait_group 0;" ::: "memory");
            }
            __syncthreads();   // chunk ch fully staged

            const uint32_t aB = sb + SM_A + buf * 8192;
            const uint32_t bB = sb + SM_B + buf * 12288;
#pragma unroll
            for (int ks = 0; ks < 4; ks++) {     // 4 k16-steps over KC=64
                uint32_t a[2][4];
#pragma unroll
                for (int mf = 0; mf < 2; mf++) {
                    int row  = m_base + mf * 16 + a_row_in;
                    int colb = ks * 32 + a_colb16;
                    ldsm4(a[mf], aB + (uint32_t)SWZ128(row * 128 + colb));
                }
                uint32_t b[6][2];
#pragma unroll
                for (int p = 0; p < 3; p++) {
                    int nrow = n_base + p * 16 + b_row_in;
                    int colb = ks * 32 + b_colb16;
                    uint32_t r[4];
                    ldsm4(r, bB + (uint32_t)SWZ128(nrow * 128 + colb));
                    b[2 * p][0] = r[0];     b[2 * p][1] = r[1];
                    b[2 * p + 1][0] = r[2]; b[2 * p + 1][1] = r[3];
                }
#pragma unroll
                for (int mf = 0; mf < 2; mf++)
#pragma unroll
                    for (int nf = 0; nf < 6; nf++)
                        mma_f16(acc[mf][nf], a[mf], b[nf]);
            }
        }

        // ---- epilogue: bias + activation -> act (fp16 half2) ----
#pragma unroll
        for (int mf = 0; mf < 2; mf++) {
            int r0 = m_base + mf * 16 + g;
#pragma unroll
            for (int nf = 0; nf < 6; nf++) {
                int j   = n_base + nf * 8 + tg * 2;
                int grp = j >> 5;
#pragma unroll
                for (int rr = 0; rr < 2; rr++) {
                    int row  = r0 + rr * 8;
                    float v0 = acc[mf][nf][rr * 2 + 0] + sbias[j];
                    float v1 = acc[mf][nf][rr * 2 + 1] + sbias[j + 1];
                    if (grp == 0) { v0 = tanh_hw(v0);    v1 = tanh_hw(v1); }
                    else          { v0 = sigmoid_hw(v0); v1 = sigmoid_hw(v1); }
                    *(__half2*)(act + row * ACT_STRIDE + j) = __floats2half2_rn(v0, v1);
                }
            }
        }
        __syncthreads();

        // ---- parallel segmented scan: warp = 16-t segment, lane = channel ----
        const int t0s = wid * 16;
        float Aseg = 1.0f, Bseg = 0.0f;
#pragma unroll
        for (int i = 0; i < 16; i++) {
            const __half* rowp = act + (t0s + i) * ACT_STRIDE;
            float z = __half2float(rowp[lane]);
            float f = __half2float(rowp[32 + lane]);
            float a = 1.0f - f;
            Aseg *= a;
            Bseg = fmaf(a, Bseg, f * z);
        }
        segA[wid * 32 + lane] = Aseg;
        segB[wid * 32 + lane] = Bseg;
        __syncthreads();

        // c at entry of my segment
        float c = c_carry;
        for (int s = 0; s < wid; s++)
            c = fmaf(segA[s * 32 + lane], c, segB[s * 32 + lane]);
        // pass 2: walk my 16 t's
#pragma unroll
        for (int i = 0; i < 16; i++) {
            const __half* rowp = act + (t0s + i) * ACT_STRIDE;
            float z = __half2float(rowp[lane]);
            float f = __half2float(rowp[32 + lane]);
            float o = __half2float(rowp[64 + lane]);
            c = fmaf(f, z - c, c);                 // c = f*z + (1-f)*c
            m_state = fmaxf(m_state, o * c);
        }
        // advance carry over the whole chunk (replicated in all warps)
#pragma unroll
        for (int s = 0; s < 4; s++)
            c_carry = fmaf(segA[s * 32 + lane], c_carry, segB[s * 32 + lane]);
        // next chunk's k-loop barriers order these reads before seg overwrite
    }

    // final: max across the 4 segment-warps of each channel
    __syncthreads();                    // seg reads done; reuse segA as staging
    segA[wid * 32 + lane] = m_state;
    __syncthreads();
    if (wid == 0) {
        float r = m_state;              // wid 0's own
#pragma unroll
        for (int s = 1; s < 4; s++) r = fmaxf(r, segA[s * 32 + lane]);
        out[bb * H_DIM + h0 + lane] = r;
    }
}

extern "C" void kernel_launch(void* const* d_in, const int* in_sizes, int n_in,
                              void* d_out, int out_size)
{
    (void)in_sizes; (void)n_in; (void)out_size;
    const float* sent = (const float*)d_in[0];   // (T,B,E) fp32
    const float* W    = (const float*)d_in[2];   // (3H,E)  fp32
    const float* bias = (const float*)d_in[3];   // (3H)    fp32
    float* out = (float*)d_out;                  // (B,H)   fp32

    cudaFuncSetAttribute(qrnn_f16_kernel, cudaFuncAttributeMaxDynamicSharedMemorySize, SMEM_BYTES);

    prep_all<<<(SENT_F4 + W_F4 + 255) / 256, 256>>>(sent, W);
    qrnn_f16_kernel<<<dim3(H_DIM / HC, B_DIM), 128, SMEM_BYTES>>>(bias, out);
}